// round 15
// baseline (speedup 1.0000x reference)
#include <cuda_runtime.h>
#include <cuda_bf16.h>
#include <math.h>

#define NPIX 9216
#define CCH  64
#define HH   96
#define WW   96
#define HS   24
#define KNN  5
#define E5   (NPIX * KNN)                /* 46080 */
#define ETOT (E5 + NPIX)                 /* 55296 */
#define NCAND 64                         /* candidates per row (8 splits x 8) */
#define SPLITS 8
#define CPS 1152                         /* cols per split */
#define TILES (CPS / 128)                /* 9 */

// ---------------- scratch (static device globals; no allocation) ----------------
__device__ float    g_hsi_up[CCH * NPIX];   // channel-major [c][pix]; also the residual
__device__ float    g_hfeat[NPIX * CCH];    // pixel-major [pix][c]
__device__ float    g_mfeat[NPIX * CCH];
__device__ unsigned short g_hbf[NPIX * CCH];  // bf16 copies, pixel-major
__device__ unsigned short g_mbf[NPIX * CCH];
__device__ float    g_z    [NPIX * CCH];
__device__ float    g_el   [NPIX];
__device__ float    g_er   [NPIX];
__device__ int      g_cidx [NPIX * NCAND];
__device__ int      g_topk [NPIX * KNN];
__device__ float    g_den  [NPIX];
__device__ float    g_agg  [CCH * NPIX];    // CHANNEL-major: spreads hot-dst atomics over LTS
__device__ float    g_up1  [CCH * NPIX];

// ---------------- helpers ----------------
__device__ __forceinline__ unsigned pack_bf16x2(float lo, float hi) {
    unsigned d;
    asm("cvt.rn.bf16x2.f32 %0, %1, %2;" : "=r"(d) : "f"(hi), "f"(lo));
    return d;
}

__device__ __forceinline__ float cubw(float d) {
    d = fabsf(d);
    const float a = -0.75f;
    if (d <= 1.0f) return ((a + 2.0f) * d - (a + 3.0f)) * d * d + 1.0f;
    if (d < 2.0f)  return ((a * d - 5.0f * a) * d + 8.0f * a) * d - 4.0f * a;
    return 0.0f;
}

// branchless sorted insert into descending 8-list of packed s32 keys (16 IMNMX)
__device__ __forceinline__ void ins8(int (&v)[8], int x) {
    #pragma unroll
    for (int s = 0; s < 8; s++) {
        int hi = max(v[s], x);
        x      = min(v[s], x);
        v[s] = hi;
    }
}

// ---------------- K1: bicubic x4 upsample, smem-staged (24x24 -> 96x96) ----------
__global__ __launch_bounds__(256) void k_bicubic(const float* __restrict__ in) {
    __shared__ float s[HS * HS];
    int c = blockIdx.x;
    for (int i = threadIdx.x; i < HS * HS; i += 256) s[i] = in[c * HS * HS + i];
    __syncthreads();
    int obase = blockIdx.y * (NPIX / 4);
    for (int o = obase + threadIdx.x; o < obase + NPIX / 4; o += 256) {
        int x = o % WW, y = o / WW;
        float fy = (y + 0.5f) * 0.25f - 0.5f;
        float iy = floorf(fy); float ty = fy - iy;
        float fx = (x + 0.5f) * 0.25f - 0.5f;
        float ix = floorf(fx); float tx = fx - ix;
        float wy[4], wx[4]; int sy[4], sx[4];
        #pragma unroll
        for (int k = 0; k < 4; k++) {
            wy[k] = cubw(ty - (float)(k - 1));
            wx[k] = cubw(tx - (float)(k - 1));
            sy[k] = min(max((int)iy + k - 1, 0), HS - 1);
            sx[k] = min(max((int)ix + k - 1, 0), HS - 1);
        }
        float acc = 0.0f;
        #pragma unroll
        for (int i = 0; i < 4; i++) {
            float r = 0.0f;
            #pragma unroll
            for (int j = 0; j < 4; j++) r = fmaf(wx[j], s[sy[i] * HS + sx[j]], r);
            acc = fmaf(wy[i], r, acc);
        }
        g_hsi_up[c * NPIX + o] = acc;
    }
}

// ---------------- K2: fused 2-layer 1x1-conv embed, both branches -----------------
__global__ __launch_bounds__(256) void k_embed(
    const float* __restrict__ X0, const float* __restrict__ X1,
    const float* __restrict__ Wa0, const float* __restrict__ ba0, const float* __restrict__ aa0,
    const float* __restrict__ Wb0, const float* __restrict__ bb0, const float* __restrict__ ab0,
    const float* __restrict__ Wa1, const float* __restrict__ ba1, const float* __restrict__ aa1,
    const float* __restrict__ Wb1, const float* __restrict__ bb1, const float* __restrict__ ab1,
    float* __restrict__ Y0, float* __restrict__ Y1,
    unsigned short* __restrict__ Yb0, unsigned short* __restrict__ Yb1)
{
    __shared__ float xs[64 * 64];
    __shared__ float ws[64 * 64];
    __shared__ float bsh[64];
    __shared__ float s_alpha;
    int br = blockIdx.y;
    const float* X  = br ? X1 : X0;
    const float* Wa = br ? Wa1 : Wa0;
    const float* ba = br ? ba1 : ba0;
    const float* aa = br ? aa1 : aa0;
    const float* Wb = br ? Wb1 : Wb0;
    const float* bb = br ? bb1 : bb0;
    const float* ab = br ? ab1 : ab0;
    float* Y = br ? Y1 : Y0;
    unsigned short* Yb = br ? Yb1 : Yb0;
    int tid = threadIdx.x;
    int tx = tid & 15, ty = tid >> 4;
    int pbase = blockIdx.x * 64;

    for (int t = tid; t < 1024; t += 256) {
        int c = t >> 4, p4 = t & 15;
        ((float4*)xs)[c * 16 + p4] = *(const float4*)(X + c * NPIX + pbase + p4 * 4);
    }
    for (int t = tid; t < 1024; t += 256)
        ((float4*)ws)[t] = ((const float4*)Wa)[t];
    if (tid < 64) bsh[tid] = ba[tid];
    if (tid == 0) s_alpha = aa[0];
    __syncthreads();

    float acc[4][4];
    #pragma unroll
    for (int j = 0; j < 4; j++)
        #pragma unroll
        for (int i = 0; i < 4; i++) acc[j][i] = bsh[ty * 4 + j];
    for (int c = 0; c < 64; c++) {
        float xv[4], wv[4];
        #pragma unroll
        for (int i = 0; i < 4; i++) xv[i] = xs[c * 64 + tx + 16 * i];
        #pragma unroll
        for (int j = 0; j < 4; j++) wv[j] = ws[(ty * 4 + j) * 64 + c];
        #pragma unroll
        for (int j = 0; j < 4; j++)
            #pragma unroll
            for (int i = 0; i < 4; i++) acc[j][i] = fmaf(wv[j], xv[i], acc[j][i]);
    }
    float al = s_alpha;
    __syncthreads();

    #pragma unroll
    for (int j = 0; j < 4; j++)
        #pragma unroll
        for (int i = 0; i < 4; i++) {
            float v = acc[j][i];
            v = (v >= 0.0f) ? v : al * v;
            xs[(ty * 4 + j) * 64 + tx + 16 * i] = v;
        }
    for (int t = tid; t < 1024; t += 256)
        ((float4*)ws)[t] = ((const float4*)Wb)[t];
    if (tid < 64) bsh[tid] = bb[tid];
    if (tid == 0) s_alpha = ab[0];
    __syncthreads();

    #pragma unroll
    for (int j = 0; j < 4; j++)
        #pragma unroll
        for (int i = 0; i < 4; i++) acc[j][i] = bsh[ty * 4 + j];
    for (int c = 0; c < 64; c++) {
        float xv[4], wv[4];
        #pragma unroll
        for (int i = 0; i < 4; i++) xv[i] = xs[c * 64 + tx + 16 * i];
        #pragma unroll
        for (int j = 0; j < 4; j++) wv[j] = ws[(ty * 4 + j) * 64 + c];
        #pragma unroll
        for (int j = 0; j < 4; j++)
            #pragma unroll
            for (int i = 0; i < 4; i++) acc[j][i] = fmaf(wv[j], xv[i], acc[j][i]);
    }
    float al2 = s_alpha;
    #pragma unroll
    for (int i = 0; i < 4; i++) {
        int pix = pbase + tx + 16 * i;
        float4 o4;
        float v;
        v = acc[0][i]; o4.x = (v >= 0.0f) ? v : al2 * v;
        v = acc[1][i]; o4.y = (v >= 0.0f) ? v : al2 * v;
        v = acc[2][i]; o4.z = (v >= 0.0f) ? v : al2 * v;
        v = acc[3][i]; o4.w = (v >= 0.0f) ? v : al2 * v;
        *(float4*)(Y + pix * 64 + ty * 4) = o4;
        uint2 b2;
        b2.x = pack_bf16x2(o4.x, o4.y);
        b2.y = pack_bf16x2(o4.z, o4.w);
        *(uint2*)(Yb + pix * 64 + ty * 4) = b2;
    }
}

// ---------------- K3: bf16 HMMA sim GEMM + packed-key top-8, float-threshold filter
// Steady-state guard per dot PAIR: 1 FMNMX + 1 FSETP vs the truncated-8th float.
// Guard is exact: c < tf  =>  trunc(c) < trunc-bits of k[7]  =>  key < k[7],
// so no admissible insert is ever skipped (bit-identical candidate sets).
#define BPITCH 72
__global__ __launch_bounds__(256, 4) void k_sim_hmma() {
    __shared__ __align__(16) unsigned short Bs[128 * BPITCH];
    int tid = threadIdx.x;
    int w = tid >> 5, lane = tid & 31;
    int rowbase = blockIdx.x * 128;
    int split = blockIdx.y;
    int colbase = split * CPS;

    int r0 = rowbase + w * 16 + (lane >> 2);
    int r1 = r0 + 8;
    int lg = lane & 3;

    unsigned a[4][4];
    #pragma unroll
    for (int ks = 0; ks < 4; ks++) {
        int k0r = ks * 16 + lg * 2;
        a[ks][0] = *(const unsigned*)(g_hbf + r0 * 64 + k0r);
        a[ks][1] = *(const unsigned*)(g_hbf + r1 * 64 + k0r);
        a[ks][2] = *(const unsigned*)(g_hbf + r0 * 64 + k0r + 8);
        a[ks][3] = *(const unsigned*)(g_hbf + r1 * 64 + k0r + 8);
    }

    int k0[8], k1[8];
    #pragma unroll
    for (int j = 0; j < 8; j++) { k0[j] = (int)0x80000000; k1[j] = (int)0x80000000; }
    float tf0 = -INFINITY, tf1 = -INFINITY;

    for (int tile = 0; tile < TILES; tile++) {
        int cbl = tile * 128;                 // local col base of tile
        __syncthreads();
        for (int q = tid; q < 1024; q += 256) {
            int n = q >> 3, c8 = q & 7;
            *(float4*)(Bs + n * BPITCH + c8 * 8) =
                *(const float4*)(g_mbf + (colbase + cbl + n) * 64 + c8 * 8);
        }
        __syncthreads();

        #pragma unroll 2
        for (int nc = 0; nc < 16; nc++) {
            int n0 = nc * 8;
            float c0 = 0.0f, c1 = 0.0f, c2 = 0.0f, c3 = 0.0f;
            const unsigned short* brow = Bs + (n0 + (lane >> 2)) * BPITCH + lg * 2;
            #pragma unroll
            for (int ks = 0; ks < 4; ks++) {
                unsigned b0 = *(const unsigned*)(brow + ks * 16);
                unsigned b1 = *(const unsigned*)(brow + ks * 16 + 8);
                asm volatile(
                    "mma.sync.aligned.m16n8k16.row.col.f32.bf16.bf16.f32 "
                    "{%0,%1,%2,%3}, {%4,%5,%6,%7}, {%8,%9}, {%0,%1,%2,%3};"
                    : "+f"(c0), "+f"(c1), "+f"(c2), "+f"(c3)
                    : "r"(a[ks][0]), "r"(a[ks][1]), "r"(a[ks][2]), "r"(a[ks][3]),
                      "r"(b0), "r"(b1));
            }
            int lidx = cbl + n0 + lg * 2;     // < 1152, fits 13 bits; even
            if (fmaxf(c0, c1) >= tf0) {
                int key0 = (__float_as_int(c0) & ~0x1FFF) | lidx;
                int key1 = (__float_as_int(c1) & ~0x1FFF) | (lidx + 1);
                if (key0 > k0[7]) ins8(k0, key0);
                if (key1 > k0[7]) ins8(k0, key1);
                tf0 = __int_as_float(k0[7] & ~0x1FFF);
            }
            if (fmaxf(c2, c3) >= tf1) {
                int key2 = (__float_as_int(c2) & ~0x1FFF) | lidx;
                int key3 = (__float_as_int(c3) & ~0x1FFF) | (lidx + 1);
                if (key2 > k1[7]) ins8(k1, key2);
                if (key3 > k1[7]) ins8(k1, key3);
                tf1 = __int_as_float(k1[7] & ~0x1FFF);
            }
        }
    }

    // merge the 4 lane-group lists (disjoint column sets) -> full-split top-8.
    #pragma unroll
    for (int lvl = 1; lvl <= 2; lvl <<= 1) {
        int o0[8], o1[8];
        #pragma unroll
        for (int j = 0; j < 8; j++) {
            o0[j] = __shfl_xor_sync(0xffffffffu, k0[j], lvl);
            o1[j] = __shfl_xor_sync(0xffffffffu, k1[j], lvl);
        }
        #pragma unroll
        for (int j = 0; j < 8; j++) {
            if (o0[j] > k0[7]) ins8(k0, o0[j]);
            if (o1[j] > k1[7]) ins8(k1, o1[j]);
        }
    }

    if (lg == 0) {
        int base0 = r0 * NCAND + split * 8;
        int base1 = r1 * NCAND + split * 8;
        #pragma unroll
        for (int j = 0; j < 8; j++) {
            g_cidx[base0 + j] = colbase + (k0[j] & 0x1FFF);
            g_cidx[base1 + j] = colbase + (k1[j] & 0x1FFF);
        }
    }
}

// ---------------- K4: exact fp32 rescore, cooperative coalesced gathers ------------
__global__ __launch_bounds__(256) void k_rescore() {
    int tid = threadIdx.x;
    int w = tid >> 5, lane = tid & 31;
    int row = blockIdx.x * 8 + w;

    float2 h = *(const float2*)(g_hfeat + row * 64 + lane * 2);
    int myc0 = g_cidx[row * NCAND + lane];
    int myc1 = g_cidx[row * NCAND + 32 + lane];

    float v[2]; int ix[2];
    ix[0] = myc0; ix[1] = myc1;
    v[0] = 0.0f; v[1] = 0.0f;

    #pragma unroll
    for (int half = 0; half < 2; half++) {
        int src = half ? myc1 : myc0;
        #pragma unroll
        for (int g = 0; g < 4; g++) {
            float p[8];
            #pragma unroll
            for (int j = 0; j < 8; j++) {
                int ci = __shfl_sync(0xffffffffu, src, g * 8 + j);
                float2 m = *(const float2*)(g_mfeat + ci * 64 + lane * 2);
                p[j] = fmaf(h.x, m.x, h.y * m.y);
            }
            #pragma unroll
            for (int j = 0; j < 8; j++) {
                #pragma unroll
                for (int off = 16; off; off >>= 1)
                    p[j] += __shfl_xor_sync(0xffffffffu, p[j], off);
            }
            #pragma unroll
            for (int j = 0; j < 8; j++)
                if (lane == g * 8 + j) v[half] = p[j];
        }
    }

    #pragma unroll
    for (int sel = 0; sel < KNN; sel++) {
        bool first = (v[0] > v[1]) || (v[0] == v[1] && ix[0] < ix[1]);
        float bv = first ? v[0] : v[1];
        int   bi = first ? ix[0] : ix[1];
        #pragma unroll
        for (int off = 16; off; off >>= 1) {
            float ov = __shfl_xor_sync(0xffffffffu, bv, off);
            int   oi = __shfl_xor_sync(0xffffffffu, bi, off);
            if (ov > bv || (ov == bv && oi < bi)) { bv = ov; bi = oi; }
        }
        if (lane == 0) g_topk[row * KNN + sel] = bi;
        if (ix[0] == bi) v[0] = -INFINITY;
        if (ix[1] == bi) v[1] = -INFINITY;
    }
}

// ---------------- K5: GAT fc  z = [hfeat|mfeat] @ Wg,  el/er per node --------------
__global__ __launch_bounds__(256) void k_gatz(const float* __restrict__ Wg,
                                              const float* __restrict__ alv,
                                              const float* __restrict__ arv) {
    __shared__ float xs[64 * 65];
    __shared__ float ws[64 * 64];
    __shared__ float als[64], ars[64];
    __shared__ float sel[64], ser[64];
    int tid = threadIdx.x, tx = tid & 15, ty = tid >> 4;
    int pbase = blockIdx.x * 64;
    if (tid < 64) { als[tid] = alv[tid]; ars[tid] = arv[tid]; sel[tid] = 0.0f; ser[tid] = 0.0f; }

    float acc[4][4];
    #pragma unroll
    for (int j = 0; j < 4; j++)
        #pragma unroll
        for (int i = 0; i < 4; i++) acc[j][i] = 0.0f;

    for (int half = 0; half < 2; half++) {
        const float* X = half ? g_mfeat : g_hfeat;
        __syncthreads();
        for (int t = tid; t < 1024; t += 256) {
            int p = t >> 4, cc = t & 15;
            float4 v = *(const float4*)(X + (pbase + p) * 64 + cc * 4);
            xs[(4 * cc + 0) * 65 + p] = v.x;
            xs[(4 * cc + 1) * 65 + p] = v.y;
            xs[(4 * cc + 2) * 65 + p] = v.z;
            xs[(4 * cc + 3) * 65 + p] = v.w;
        }
        for (int t = tid; t < 1024; t += 256)
            ((float4*)ws)[t] = ((const float4*)(Wg + half * 64 * 64))[t];
        __syncthreads();
        for (int c = 0; c < 64; c++) {
            float xv[4];
            #pragma unroll
            for (int i = 0; i < 4; i++) xv[i] = xs[c * 65 + tx + 16 * i];
            float4 w4 = *(const float4*)(ws + c * 64 + ty * 4);
            float wv[4] = {w4.x, w4.y, w4.z, w4.w};
            #pragma unroll
            for (int j = 0; j < 4; j++)
                #pragma unroll
                for (int i = 0; i < 4; i++) acc[j][i] = fmaf(wv[j], xv[i], acc[j][i]);
        }
    }

    float a_l[4], a_r[4];
    #pragma unroll
    for (int j = 0; j < 4; j++) { a_l[j] = als[ty * 4 + j]; a_r[j] = ars[ty * 4 + j]; }
    #pragma unroll
    for (int i = 0; i < 4; i++) {
        int p = pbase + tx + 16 * i;
        float4 z4 = make_float4(acc[0][i], acc[1][i], acc[2][i], acc[3][i]);
        *(float4*)(g_z + p * 64 + ty * 4) = z4;
        float e_l = 0.0f, e_r = 0.0f;
        #pragma unroll
        for (int j = 0; j < 4; j++) {
            e_l = fmaf(acc[j][i], a_l[j], e_l);
            e_r = fmaf(acc[j][i], a_r[j], e_r);
        }
        atomicAdd(&sel[tx + 16 * i], e_l);
        atomicAdd(&ser[tx + 16 * i], e_r);
    }
    __syncthreads();
    if (tid < 64) {
        g_el[pbase + tid] = sel[tid];
        g_er[pbase + tid] = ser[tid];
        g_den[pbase + tid] = 0.0f;
    }
}

// ---------------- K6: softmax denominator over ALL edges (k-NN + self loops) -------
__global__ void k_edge_den() {
    int e = blockIdx.x * blockDim.x + threadIdx.x;
    if (e >= ETOT) return;
    int src, dst;
    if (e < E5) { src = e % NPIX; dst = g_topk[e]; }
    else        { src = e - E5;   dst = src; }
    float l = g_el[src] + g_er[dst];
    l = (l >= 0.0f) ? l : 0.2f * l;
    atomicAdd(&g_den[dst], expf(l));
}

// ---------------- K7: self-loop init of channel-major agg (+bias), fused transpose -
__global__ __launch_bounds__(256) void k_selfagg(const float* __restrict__ bg) {
    __shared__ float tb[64 * 65];
    __shared__ float bs[64];
    __shared__ float sal[64];
    int tid = threadIdx.x;
    int nb = blockIdx.x * 64;
    if (tid < 64) {
        bs[tid] = bg[tid];
        int n = nb + tid;
        float l = g_el[n] + g_er[n];
        l = (l >= 0.0f) ? l : 0.2f * l;
        sal[tid] = expf(l) / g_den[n];
    }
    for (int t = tid; t < 1024; t += 256) {
        int p = t >> 4, cc = t & 15;
        float4 v = *(const float4*)(g_z + (nb + p) * 64 + cc * 4);
        tb[(4 * cc + 0) * 65 + p] = v.x;
        tb[(4 * cc + 1) * 65 + p] = v.y;
        tb[(4 * cc + 2) * 65 + p] = v.z;
        tb[(4 * cc + 3) * 65 + p] = v.w;
    }
    __syncthreads();
    for (int k = 0; k < 16; k++) {
        int idx = tid + k * 256;
        int c = idx >> 6, nn = idx & 63;
        g_agg[c * NPIX + nb + nn] = fmaf(tb[c * 65 + nn], sal[nn], bs[c]);
    }
}

// ---------------- K8: k-NN edge aggregation, channel-major atomics -----------------
__global__ void k_edge_agg() {
    int t = blockIdx.x * blockDim.x + threadIdx.x;
    int e = t >> 2;
    if (e >= E5) return;
    int c0 = (t & 3) * 16;
    int src = e % NPIX;
    int dst = g_topk[e];
    float l = g_el[src] + g_er[dst];
    l = (l >= 0.0f) ? l : 0.2f * l;
    float alpha = expf(l) / g_den[dst];
    const float* zs = g_z + src * 64 + c0;
    #pragma unroll
    for (int c = 0; c < 16; c++)
        atomicAdd(&g_agg[(c0 + c) * NPIX + dst], alpha * zs[c]);
}

// ---------------- K9: 3x3 conv, 8-out-channel groups, 2 CTAs/SM --------------------
#define OGRP 8
__global__ __launch_bounds__(256, 2) void k_conv3x3(const float* __restrict__ In,
                                                    const float* __restrict__ Kw,
                                                    const float* __restrict__ bias,
                                                    const float* __restrict__ aptr,
                                                    float* __restrict__ Out,
                                                    const float* __restrict__ resid) {
    __shared__ float ws[OGRP * 64 * 9];   // 18432 B
    __shared__ float tile[4][324];
    int og = blockIdx.z * OGRP;
    for (int i = threadIdx.x; i < OGRP * 64 * 9; i += 256) ws[i] = Kw[og * 576 + i];
    float alpha = aptr[0];
    int sub = threadIdx.x >> 6;          // 0..3 -> 2 outputs each
    int q   = threadIdx.x & 63;
    int qx  = q & 3, y = q >> 2;
    int x0 = blockIdx.x * 16, y0 = blockIdx.y * 16;
    float acc[2][4];
    #pragma unroll
    for (int j = 0; j < 2; j++) {
        float b = bias[og + sub * 2 + j];
        #pragma unroll
        for (int i = 0; i < 4; i++) acc[j][i] = b;
    }
    for (int cs = 0; cs < 64; cs += 4) {
        __syncthreads();
        for (int i = threadIdx.x; i < 1296; i += 256) {
            int cc = i / 324, p = i - cc * 324;
            int lx = p % 18 - 1 + x0;
            int ly = p / 18 - 1 + y0;
            tile[cc][p] = (lx >= 0 && lx < WW && ly >= 0 && ly < HH)
                            ? In[(cs + cc) * NPIX + ly * WW + lx] : 0.0f;
        }
        __syncthreads();
        #pragma unroll
        for (int cc = 0; cc < 4; cc++) {
            float r[3][6];
            #pragma unroll
            for (int ky = 0; ky < 3; ky++)
                #pragma unroll
                for (int m = 0; m < 6; m++)
                    r[ky][m] = tile[cc][(y + ky) * 18 + qx * 4 + m];
            #pragma unroll
            for (int j = 0; j < 2; j++) {
                const float* w = ws + ((sub * 2 + j) * 64 + cs + cc) * 9;
                float wv[9];
                #pragma unroll
                for (int k = 0; k < 9; k++) wv[k] = w[k];
                #pragma unroll
                for (int i = 0; i < 4; i++)
                    #pragma unroll
                    for (int ky = 0; ky < 3; ky++)
                        #pragma unroll
                        for (int kx = 0; kx < 3; kx++)
                            acc[j][i] = fmaf(wv[ky * 3 + kx], r[ky][kx + i], acc[j][i]);
            }
        }
    }
    int pix0 = (y0 + y) * WW + x0 + qx * 4;
    #pragma unroll
    for (int j = 0; j < 2; j++) {
        int o = og + sub * 2 + j;
        float4 v4;
        float v;
        v = acc[j][0]; v4.x = (v >= 0.0f) ? v : alpha * v;
        v = acc[j][1]; v4.y = (v >= 0.0f) ? v : alpha * v;
        v = acc[j][2]; v4.z = (v >= 0.0f) ? v : alpha * v;
        v = acc[j][3]; v4.w = (v >= 0.0f) ? v : alpha * v;
        if (resid) {
            float4 rr = *(const float4*)(resid + o * NPIX + pix0);
            v4.x += rr.x; v4.y += rr.y; v4.z += rr.z; v4.w += rr.w;
        }
        *(float4*)(Out + o * NPIX + pix0) = v4;
    }
}

// ---------------- launch ----------------
extern "C" void kernel_launch(void* const* d_in, const int* in_sizes, int n_in,
                              void* d_out, int out_size) {
    const float* msi  = (const float*)d_in[0];
    const float* hsi  = (const float*)d_in[1];
    const float* W1a  = (const float*)d_in[2];
    const float* b1a  = (const float*)d_in[3];
    const float* a1a  = (const float*)d_in[4];
    const float* W1b  = (const float*)d_in[5];
    const float* b1b  = (const float*)d_in[6];
    const float* a1b  = (const float*)d_in[7];
    const float* W2a  = (const float*)d_in[8];
    const float* b2a  = (const float*)d_in[9];
    const float* a2a  = (const float*)d_in[10];
    const float* W2b  = (const float*)d_in[11];
    const float* b2b  = (const float*)d_in[12];
    const float* a2b  = (const float*)d_in[13];
    const float* Wg   = (const float*)d_in[14];
    const float* attl = (const float*)d_in[15];
    const float* attr = (const float*)d_in[16];
    const float* bg   = (const float*)d_in[17];
    const float* Ku1  = (const float*)d_in[18];
    const float* bu1  = (const float*)d_in[19];
    const float* au1  = (const float*)d_in[20];
    const float* Ku2  = (const float*)d_in[21];
    const float* bu2  = (const float*)d_in[22];
    const float* au2  = (const float*)d_in[23];

    float *p_hsi_up, *p_hfeat, *p_mfeat, *p_agg, *p_up1;
    unsigned short *p_hbf, *p_mbf;
    cudaGetSymbolAddress((void**)&p_hsi_up, g_hsi_up);
    cudaGetSymbolAddress((void**)&p_hfeat,  g_hfeat);
    cudaGetSymbolAddress((void**)&p_mfeat,  g_mfeat);
    cudaGetSymbolAddress((void**)&p_agg,    g_agg);
    cudaGetSymbolAddress((void**)&p_up1,    g_up1);
    cudaGetSymbolAddress((void**)&p_hbf,    g_hbf);
    cudaGetSymbolAddress((void**)&p_mbf,    g_mbf);

    k_bicubic<<<dim3(CCH, 4), 256>>>(hsi);

    k_embed<<<dim3(NPIX / 64, 2), 256>>>(p_hsi_up, msi,
                                         W1a, b1a, a1a, W1b, b1b, a1b,
                                         W2a, b2a, a2a, W2b, b2b, a2b,
                                         p_hfeat, p_mfeat, p_hbf, p_mbf);

    k_gatz<<<NPIX / 64, 256>>>(Wg, attl, attr);

    k_sim_hmma<<<dim3(72, SPLITS), 256>>>();
    k_rescore<<<NPIX / 8, 256>>>();

    k_edge_den<<<(ETOT + 255) / 256, 256>>>();
    k_selfagg<<<NPIX / 64, 256>>>(bg);
    k_edge_agg<<<(E5 * 4 + 255) / 256, 256>>>();

    k_conv3x3<<<dim3(6, 6, 8), 256>>>(p_agg, Ku1, bu1, au1, p_up1, nullptr);
    k_conv3x3<<<dim3(6, 6, 8), 256>>>(p_up1, Ku2, bu2, au2, (float*)d_out, p_hsi_up);
}

// round 16
// speedup vs baseline: 1.0939x; 1.0939x over previous
#include <cuda_runtime.h>
#include <cuda_bf16.h>
#include <math.h>

#define NPIX 9216
#define CCH  64
#define HH   96
#define WW   96
#define HS   24
#define KNN  5
#define E5   (NPIX * KNN)                /* 46080 */
#define ETOT (E5 + NPIX)                 /* 55296 */
#define NCAND 64                         /* candidates per row (8 splits x 8) */
#define SPLITS 8
#define CPS 1152                         /* cols per split */
#define TILES (CPS / 128)                /* 9 */

// ---------------- scratch (static device globals; no allocation) ----------------
__device__ float    g_hsi_up[CCH * NPIX];   // channel-major [c][pix]; also the residual
__device__ float    g_hfeat[NPIX * CCH];    // pixel-major [pix][c]
__device__ float    g_mfeat[NPIX * CCH];
__device__ unsigned short g_hbf[NPIX * CCH];  // bf16 copies, pixel-major
__device__ unsigned short g_mbf[NPIX * CCH];
__device__ float    g_z    [NPIX * CCH];
__device__ float    g_el   [NPIX];
__device__ float    g_er   [NPIX];
__device__ int      g_cidx [NPIX * NCAND];
__device__ int      g_topk [NPIX * KNN];
__device__ float    g_den  [NPIX];
__device__ float    g_agg  [CCH * NPIX];    // CHANNEL-major: spreads hot-dst atomics over LTS
__device__ float    g_up1  [CCH * NPIX];

// ---------------- helpers ----------------
__device__ __forceinline__ unsigned pack_bf16x2(float lo, float hi) {
    unsigned d;
    asm("cvt.rn.bf16x2.f32 %0, %1, %2;" : "=r"(d) : "f"(hi), "f"(lo));
    return d;
}

__device__ __forceinline__ float cubw(float d) {
    d = fabsf(d);
    const float a = -0.75f;
    if (d <= 1.0f) return ((a + 2.0f) * d - (a + 3.0f)) * d * d + 1.0f;
    if (d < 2.0f)  return ((a * d - 5.0f * a) * d + 8.0f * a) * d - 4.0f * a;
    return 0.0f;
}

// compare-exchange: max to a, min to b
#define CS(a, b) do { int _hi = max(a, b); b = min(a, b); a = _hi; } while (0)

// list = top-8(list ∪ buf4). sort4 desc + half-cleaner + 8-wide bitonic merge.
// Exact by the bitonic half-cleaner theorem; all keys distinct (lidx embedded).
__device__ __forceinline__ void merge4(int (&k)[8], int (&b)[4]) {
    // sort b descending (5 CS)
    CS(b[0], b[1]); CS(b[2], b[3]);
    CS(b[0], b[2]); CS(b[1], b[3]);
    CS(b[1], b[2]);
    // half-cleaner vs padded reverse (4 max)
    k[4] = max(k[4], b[3]);
    k[5] = max(k[5], b[2]);
    k[6] = max(k[6], b[1]);
    k[7] = max(k[7], b[0]);
    // bitonic merge descending (12 CS)
    CS(k[0], k[4]); CS(k[1], k[5]); CS(k[2], k[6]); CS(k[3], k[7]);
    CS(k[0], k[2]); CS(k[1], k[3]); CS(k[4], k[6]); CS(k[5], k[7]);
    CS(k[0], k[1]); CS(k[2], k[3]); CS(k[4], k[5]); CS(k[6], k[7]);
}

// branchless sorted insert (used only in the tiny end-of-kernel lane merge)
__device__ __forceinline__ void ins8(int (&v)[8], int x) {
    #pragma unroll
    for (int s = 0; s < 8; s++) {
        int hi = max(v[s], x);
        x      = min(v[s], x);
        v[s] = hi;
    }
}

// ---------------- K1: bicubic x4 upsample, smem-staged (24x24 -> 96x96) ----------
__global__ __launch_bounds__(256) void k_bicubic(const float* __restrict__ in) {
    __shared__ float s[HS * HS];
    int c = blockIdx.x;
    for (int i = threadIdx.x; i < HS * HS; i += 256) s[i] = in[c * HS * HS + i];
    __syncthreads();
    int obase = blockIdx.y * (NPIX / 4);
    for (int o = obase + threadIdx.x; o < obase + NPIX / 4; o += 256) {
        int x = o % WW, y = o / WW;
        float fy = (y + 0.5f) * 0.25f - 0.5f;
        float iy = floorf(fy); float ty = fy - iy;
        float fx = (x + 0.5f) * 0.25f - 0.5f;
        float ix = floorf(fx); float tx = fx - ix;
        float wy[4], wx[4]; int sy[4], sx[4];
        #pragma unroll
        for (int k = 0; k < 4; k++) {
            wy[k] = cubw(ty - (float)(k - 1));
            wx[k] = cubw(tx - (float)(k - 1));
            sy[k] = min(max((int)iy + k - 1, 0), HS - 1);
            sx[k] = min(max((int)ix + k - 1, 0), HS - 1);
        }
        float acc = 0.0f;
        #pragma unroll
        for (int i = 0; i < 4; i++) {
            float r = 0.0f;
            #pragma unroll
            for (int j = 0; j < 4; j++) r = fmaf(wx[j], s[sy[i] * HS + sx[j]], r);
            acc = fmaf(wy[i], r, acc);
        }
        g_hsi_up[c * NPIX + o] = acc;
    }
}

// ---------------- K2: fused 2-layer 1x1-conv embed, both branches -----------------
__global__ __launch_bounds__(256) void k_embed(
    const float* __restrict__ X0, const float* __restrict__ X1,
    const float* __restrict__ Wa0, const float* __restrict__ ba0, const float* __restrict__ aa0,
    const float* __restrict__ Wb0, const float* __restrict__ bb0, const float* __restrict__ ab0,
    const float* __restrict__ Wa1, const float* __restrict__ ba1, const float* __restrict__ aa1,
    const float* __restrict__ Wb1, const float* __restrict__ bb1, const float* __restrict__ ab1,
    float* __restrict__ Y0, float* __restrict__ Y1,
    unsigned short* __restrict__ Yb0, unsigned short* __restrict__ Yb1)
{
    __shared__ float xs[64 * 64];
    __shared__ float ws[64 * 64];
    __shared__ float bsh[64];
    __shared__ float s_alpha;
    int br = blockIdx.y;
    const float* X  = br ? X1 : X0;
    const float* Wa = br ? Wa1 : Wa0;
    const float* ba = br ? ba1 : ba0;
    const float* aa = br ? aa1 : aa0;
    const float* Wb = br ? Wb1 : Wb0;
    const float* bb = br ? bb1 : bb0;
    const float* ab = br ? ab1 : ab0;
    float* Y = br ? Y1 : Y0;
    unsigned short* Yb = br ? Yb1 : Yb0;
    int tid = threadIdx.x;
    int tx = tid & 15, ty = tid >> 4;
    int pbase = blockIdx.x * 64;

    for (int t = tid; t < 1024; t += 256) {
        int c = t >> 4, p4 = t & 15;
        ((float4*)xs)[c * 16 + p4] = *(const float4*)(X + c * NPIX + pbase + p4 * 4);
    }
    for (int t = tid; t < 1024; t += 256)
        ((float4*)ws)[t] = ((const float4*)Wa)[t];
    if (tid < 64) bsh[tid] = ba[tid];
    if (tid == 0) s_alpha = aa[0];
    __syncthreads();

    float acc[4][4];
    #pragma unroll
    for (int j = 0; j < 4; j++)
        #pragma unroll
        for (int i = 0; i < 4; i++) acc[j][i] = bsh[ty * 4 + j];
    for (int c = 0; c < 64; c++) {
        float xv[4], wv[4];
        #pragma unroll
        for (int i = 0; i < 4; i++) xv[i] = xs[c * 64 + tx + 16 * i];
        #pragma unroll
        for (int j = 0; j < 4; j++) wv[j] = ws[(ty * 4 + j) * 64 + c];
        #pragma unroll
        for (int j = 0; j < 4; j++)
            #pragma unroll
            for (int i = 0; i < 4; i++) acc[j][i] = fmaf(wv[j], xv[i], acc[j][i]);
    }
    float al = s_alpha;
    __syncthreads();

    #pragma unroll
    for (int j = 0; j < 4; j++)
        #pragma unroll
        for (int i = 0; i < 4; i++) {
            float v = acc[j][i];
            v = (v >= 0.0f) ? v : al * v;
            xs[(ty * 4 + j) * 64 + tx + 16 * i] = v;
        }
    for (int t = tid; t < 1024; t += 256)
        ((float4*)ws)[t] = ((const float4*)Wb)[t];
    if (tid < 64) bsh[tid] = bb[tid];
    if (tid == 0) s_alpha = ab[0];
    __syncthreads();

    #pragma unroll
    for (int j = 0; j < 4; j++)
        #pragma unroll
        for (int i = 0; i < 4; i++) acc[j][i] = bsh[ty * 4 + j];
    for (int c = 0; c < 64; c++) {
        float xv[4], wv[4];
        #pragma unroll
        for (int i = 0; i < 4; i++) xv[i] = xs[c * 64 + tx + 16 * i];
        #pragma unroll
        for (int j = 0; j < 4; j++) wv[j] = ws[(ty * 4 + j) * 64 + c];
        #pragma unroll
        for (int j = 0; j < 4; j++)
            #pragma unroll
            for (int i = 0; i < 4; i++) acc[j][i] = fmaf(wv[j], xv[i], acc[j][i]);
    }
    float al2 = s_alpha;
    #pragma unroll
    for (int i = 0; i < 4; i++) {
        int pix = pbase + tx + 16 * i;
        float4 o4;
        float v;
        v = acc[0][i]; o4.x = (v >= 0.0f) ? v : al2 * v;
        v = acc[1][i]; o4.y = (v >= 0.0f) ? v : al2 * v;
        v = acc[2][i]; o4.z = (v >= 0.0f) ? v : al2 * v;
        v = acc[3][i]; o4.w = (v >= 0.0f) ? v : al2 * v;
        *(float4*)(Y + pix * 64 + ty * 4) = o4;
        uint2 b2;
        b2.x = pack_bf16x2(o4.x, o4.y);
        b2.y = pack_bf16x2(o4.z, o4.w);
        *(uint2*)(Yb + pix * 64 + ty * 4) = b2;
    }
}

// ---------------- K3: bf16 HMMA sim GEMM + batched bitonic top-8 -------------------
// Per 2 groups: buffer 4 packed keys per list, then UNCONDITIONAL merge network
// (sort4 + half-clean + bitonic8 = 21 CS-ops) — no data-dependent branches,
// ILP-parallel stages. Output candidate sets bit-identical to sorted-insert.
#define BPITCH 72
__global__ __launch_bounds__(256, 4) void k_sim_hmma() {
    __shared__ __align__(16) unsigned short Bs[128 * BPITCH];
    int tid = threadIdx.x;
    int w = tid >> 5, lane = tid & 31;
    int rowbase = blockIdx.x * 128;
    int split = blockIdx.y;
    int colbase = split * CPS;

    int r0 = rowbase + w * 16 + (lane >> 2);
    int r1 = r0 + 8;
    int lg = lane & 3;

    unsigned a[4][4];
    #pragma unroll
    for (int ks = 0; ks < 4; ks++) {
        int k0r = ks * 16 + lg * 2;
        a[ks][0] = *(const unsigned*)(g_hbf + r0 * 64 + k0r);
        a[ks][1] = *(const unsigned*)(g_hbf + r1 * 64 + k0r);
        a[ks][2] = *(const unsigned*)(g_hbf + r0 * 64 + k0r + 8);
        a[ks][3] = *(const unsigned*)(g_hbf + r1 * 64 + k0r + 8);
    }

    int k0[8], k1[8];
    #pragma unroll
    for (int j = 0; j < 8; j++) { k0[j] = (int)0x80000000; k1[j] = (int)0x80000000; }

    for (int tile = 0; tile < TILES; tile++) {
        int cbl = tile * 128;                 // local col base of tile
        __syncthreads();
        for (int q = tid; q < 1024; q += 256) {
            int n = q >> 3, c8 = q & 7;
            *(float4*)(Bs + n * BPITCH + c8 * 8) =
                *(const float4*)(g_mbf + (colbase + cbl + n) * 64 + c8 * 8);
        }
        __syncthreads();

        #pragma unroll 2
        for (int pair = 0; pair < 8; pair++) {   // 2 groups per iteration
            int bu0[4], bu1[4];
            #pragma unroll
            for (int g = 0; g < 2; g++) {
                int nc = pair * 2 + g;
                int n0 = nc * 8;
                float c0 = 0.0f, c1 = 0.0f, c2 = 0.0f, c3 = 0.0f;
                const unsigned short* brow = Bs + (n0 + (lane >> 2)) * BPITCH + lg * 2;
                #pragma unroll
                for (int ks = 0; ks < 4; ks++) {
                    unsigned b0 = *(const unsigned*)(brow + ks * 16);
                    unsigned b1 = *(const unsigned*)(brow + ks * 16 + 8);
                    asm volatile(
                        "mma.sync.aligned.m16n8k16.row.col.f32.bf16.bf16.f32 "
                        "{%0,%1,%2,%3}, {%4,%5,%6,%7}, {%8,%9}, {%0,%1,%2,%3};"
                        : "+f"(c0), "+f"(c1), "+f"(c2), "+f"(c3)
                        : "r"(a[ks][0]), "r"(a[ks][1]), "r"(a[ks][2]), "r"(a[ks][3]),
                          "r"(b0), "r"(b1));
                }
                int lidx = cbl + n0 + lg * 2;     // < 1152, fits 13 bits; even
                bu0[2 * g]     = (__float_as_int(c0) & ~0x1FFF) | lidx;
                bu0[2 * g + 1] = (__float_as_int(c1) & ~0x1FFF) | (lidx + 1);
                bu1[2 * g]     = (__float_as_int(c2) & ~0x1FFF) | lidx;
                bu1[2 * g + 1] = (__float_as_int(c3) & ~0x1FFF) | (lidx + 1);
            }
            merge4(k0, bu0);
            merge4(k1, bu1);
        }
    }

    // merge the 4 lane-group lists (disjoint column sets) -> full-split top-8.
    #pragma unroll
    for (int lvl = 1; lvl <= 2; lvl <<= 1) {
        int o0[8], o1[8];
        #pragma unroll
        for (int j = 0; j < 8; j++) {
            o0[j] = __shfl_xor_sync(0xffffffffu, k0[j], lvl);
            o1[j] = __shfl_xor_sync(0xffffffffu, k1[j], lvl);
        }
        #pragma unroll
        for (int j = 0; j < 8; j++) {
            if (o0[j] > k0[7]) ins8(k0, o0[j]);
            if (o1[j] > k1[7]) ins8(k1, o1[j]);
        }
    }

    if (lg == 0) {
        int base0 = r0 * NCAND + split * 8;
        int base1 = r1 * NCAND + split * 8;
        #pragma unroll
        for (int j = 0; j < 8; j++) {
            g_cidx[base0 + j] = colbase + (k0[j] & 0x1FFF);
            g_cidx[base1 + j] = colbase + (k1[j] & 0x1FFF);
        }
    }
}

// ---------------- K4: exact fp32 rescore, cooperative coalesced gathers ------------
__global__ __launch_bounds__(256) void k_rescore() {
    int tid = threadIdx.x;
    int w = tid >> 5, lane = tid & 31;
    int row = blockIdx.x * 8 + w;

    float2 h = *(const float2*)(g_hfeat + row * 64 + lane * 2);
    int myc0 = g_cidx[row * NCAND + lane];
    int myc1 = g_cidx[row * NCAND + 32 + lane];

    float v[2]; int ix[2];
    ix[0] = myc0; ix[1] = myc1;
    v[0] = 0.0f; v[1] = 0.0f;

    #pragma unroll
    for (int half = 0; half < 2; half++) {
        int src = half ? myc1 : myc0;
        #pragma unroll
        for (int g = 0; g < 4; g++) {
            float p[8];
            #pragma unroll
            for (int j = 0; j < 8; j++) {
                int ci = __shfl_sync(0xffffffffu, src, g * 8 + j);
                float2 m = *(const float2*)(g_mfeat + ci * 64 + lane * 2);
                p[j] = fmaf(h.x, m.x, h.y * m.y);
            }
            #pragma unroll
            for (int j = 0; j < 8; j++) {
                #pragma unroll
                for (int off = 16; off; off >>= 1)
                    p[j] += __shfl_xor_sync(0xffffffffu, p[j], off);
            }
            #pragma unroll
            for (int j = 0; j < 8; j++)
                if (lane == g * 8 + j) v[half] = p[j];
        }
    }

    #pragma unroll
    for (int sel = 0; sel < KNN; sel++) {
        bool first = (v[0] > v[1]) || (v[0] == v[1] && ix[0] < ix[1]);
        float bv = first ? v[0] : v[1];
        int   bi = first ? ix[0] : ix[1];
        #pragma unroll
        for (int off = 16; off; off >>= 1) {
            float ov = __shfl_xor_sync(0xffffffffu, bv, off);
            int   oi = __shfl_xor_sync(0xffffffffu, bi, off);
            if (ov > bv || (ov == bv && oi < bi)) { bv = ov; bi = oi; }
        }
        if (lane == 0) g_topk[row * KNN + sel] = bi;
        if (ix[0] == bi) v[0] = -INFINITY;
        if (ix[1] == bi) v[1] = -INFINITY;
    }
}

// ---------------- K5: GAT fc  z = [hfeat|mfeat] @ Wg,  el/er per node --------------
__global__ __launch_bounds__(256) void k_gatz(const float* __restrict__ Wg,
                                              const float* __restrict__ alv,
                                              const float* __restrict__ arv) {
    __shared__ float xs[64 * 65];
    __shared__ float ws[64 * 64];
    __shared__ float als[64], ars[64];
    __shared__ float sel[64], ser[64];
    int tid = threadIdx.x, tx = tid & 15, ty = tid >> 4;
    int pbase = blockIdx.x * 64;
    if (tid < 64) { als[tid] = alv[tid]; ars[tid] = arv[tid]; sel[tid] = 0.0f; ser[tid] = 0.0f; }

    float acc[4][4];
    #pragma unroll
    for (int j = 0; j < 4; j++)
        #pragma unroll
        for (int i = 0; i < 4; i++) acc[j][i] = 0.0f;

    for (int half = 0; half < 2; half++) {
        const float* X = half ? g_mfeat : g_hfeat;
        __syncthreads();
        for (int t = tid; t < 1024; t += 256) {
            int p = t >> 4, cc = t & 15;
            float4 v = *(const float4*)(X + (pbase + p) * 64 + cc * 4);
            xs[(4 * cc + 0) * 65 + p] = v.x;
            xs[(4 * cc + 1) * 65 + p] = v.y;
            xs[(4 * cc + 2) * 65 + p] = v.z;
            xs[(4 * cc + 3) * 65 + p] = v.w;
        }
        for (int t = tid; t < 1024; t += 256)
            ((float4*)ws)[t] = ((const float4*)(Wg + half * 64 * 64))[t];
        __syncthreads();
        for (int c = 0; c < 64; c++) {
            float xv[4];
            #pragma unroll
            for (int i = 0; i < 4; i++) xv[i] = xs[c * 65 + tx + 16 * i];
            float4 w4 = *(const float4*)(ws + c * 64 + ty * 4);
            float wv[4] = {w4.x, w4.y, w4.z, w4.w};
            #pragma unroll
            for (int j = 0; j < 4; j++)
                #pragma unroll
                for (int i = 0; i < 4; i++) acc[j][i] = fmaf(wv[j], xv[i], acc[j][i]);
        }
    }

    float a_l[4], a_r[4];
    #pragma unroll
    for (int j = 0; j < 4; j++) { a_l[j] = als[ty * 4 + j]; a_r[j] = ars[ty * 4 + j]; }
    #pragma unroll
    for (int i = 0; i < 4; i++) {
        int p = pbase + tx + 16 * i;
        float4 z4 = make_float4(acc[0][i], acc[1][i], acc[2][i], acc[3][i]);
        *(float4*)(g_z + p * 64 + ty * 4) = z4;
        float e_l = 0.0f, e_r = 0.0f;
        #pragma unroll
        for (int j = 0; j < 4; j++) {
            e_l = fmaf(acc[j][i], a_l[j], e_l);
            e_r = fmaf(acc[j][i], a_r[j], e_r);
        }
        atomicAdd(&sel[tx + 16 * i], e_l);
        atomicAdd(&ser[tx + 16 * i], e_r);
    }
    __syncthreads();
    if (tid < 64) {
        g_el[pbase + tid] = sel[tid];
        g_er[pbase + tid] = ser[tid];
        g_den[pbase + tid] = 0.0f;
    }
}

// ---------------- K6: softmax denominator over ALL edges (k-NN + self loops) -------
__global__ void k_edge_den() {
    int e = blockIdx.x * blockDim.x + threadIdx.x;
    if (e >= ETOT) return;
    int src, dst;
    if (e < E5) { src = e % NPIX; dst = g_topk[e]; }
    else        { src = e - E5;   dst = src; }
    float l = g_el[src] + g_er[dst];
    l = (l >= 0.0f) ? l : 0.2f * l;
    atomicAdd(&g_den[dst], expf(l));
}

// ---------------- K7: self-loop init of channel-major agg (+bias), fused transpose -
__global__ __launch_bounds__(256) void k_selfagg(const float* __restrict__ bg) {
    __shared__ float tb[64 * 65];
    __shared__ float bs[64];
    __shared__ float sal[64];
    int tid = threadIdx.x;
    int nb = blockIdx.x * 64;
    if (tid < 64) {
        bs[tid] = bg[tid];
        int n = nb + tid;
        float l = g_el[n] + g_er[n];
        l = (l >= 0.0f) ? l : 0.2f * l;
        sal[tid] = expf(l) / g_den[n];
    }
    for (int t = tid; t < 1024; t += 256) {
        int p = t >> 4, cc = t & 15;
        float4 v = *(const float4*)(g_z + (nb + p) * 64 + cc * 4);
        tb[(4 * cc + 0) * 65 + p] = v.x;
        tb[(4 * cc + 1) * 65 + p] = v.y;
        tb[(4 * cc + 2) * 65 + p] = v.z;
        tb[(4 * cc + 3) * 65 + p] = v.w;
    }
    __syncthreads();
    for (int k = 0; k < 16; k++) {
        int idx = tid + k * 256;
        int c = idx >> 6, nn = idx & 63;
        g_agg[c * NPIX + nb + nn] = fmaf(tb[c * 65 + nn], sal[nn], bs[c]);
    }
}

// ---------------- K8: k-NN edge aggregation, channel-major atomics -----------------
__global__ void k_edge_agg() {
    int t = blockIdx.x * blockDim.x + threadIdx.x;
    int e = t >> 2;
    if (e >= E5) return;
    int c0 = (t & 3) * 16;
    int src = e % NPIX;
    int dst = g_topk[e];
    float l = g_el[src] + g_er[dst];
    l = (l >= 0.0f) ? l : 0.2f * l;
    float alpha = expf(l) / g_den[dst];
    const float* zs = g_z + src * 64 + c0;
    #pragma unroll
    for (int c = 0; c < 16; c++)
        atomicAdd(&g_agg[(c0 + c) * NPIX + dst], alpha * zs[c]);
}

// ---------------- K9: 3x3 conv, 16-out-channel groups (R14 version) ----------------
__global__ __launch_bounds__(256) void k_conv3x3(const float* __restrict__ In,
                                                 const float* __restrict__ Kw,
                                                 const float* __restrict__ bias,
                                                 const float* __restrict__ aptr,
                                                 float* __restrict__ Out,
                                                 const float* __restrict__ resid) {
    __shared__ float ws[16 * 64 * 9];   // 36864 B
    __shared__ float tile[4][324];
    int og = blockIdx.z * 16;
    for (int i = threadIdx.x; i < 16 * 64 * 9; i += 256) ws[i] = Kw[og * 576 + i];
    float alpha = aptr[0];
    int sub = threadIdx.x >> 6;
    int q   = threadIdx.x & 63;
    int qx  = q & 3, y = q >> 2;
    int x0 = blockIdx.x * 16, y0 = blockIdx.y * 16;
    float acc[4][4];
    #pragma unroll
    for (int j = 0; j < 4; j++) {
        float b = bias[og + sub * 4 + j];
        #pragma unroll
        for (int i = 0; i < 4; i++) acc[j][i] = b;
    }
    for (int cs = 0; cs < 64; cs += 4) {
        __syncthreads();
        for (int i = threadIdx.x; i < 1296; i += 256) {
            int cc = i / 324, p = i - cc * 324;
            int lx = p % 18 - 1 + x0;
            int ly = p / 18 - 1 + y0;
            tile[cc][p] = (lx >= 0 && lx < WW && ly >= 0 && ly < HH)
                            ? In[(cs + cc) * NPIX + ly * WW + lx] : 0.0f;
        }
        __syncthreads();
        #pragma unroll
        for (int cc = 0; cc < 4; cc++) {
            float r[3][6];
            #pragma unroll
            for (int ky = 0; ky < 3; ky++)
                #pragma unroll
                for (int m = 0; m < 6; m++)
                    r[ky][m] = tile[cc][(y + ky) * 18 + qx * 4 + m];
            #pragma unroll
            for (int j = 0; j < 4; j++) {
                const float* w = ws + ((sub * 4 + j) * 64 + cs + cc) * 9;
                float wv[9];
                #pragma unroll
                for (int k = 0; k < 9; k++) wv[k] = w[k];
                #pragma unroll
                for (int i = 0; i < 4; i++)
                    #pragma unroll
                    for (int ky = 0; ky < 3; ky++)
                        #pragma unroll
                        for (int kx = 0; kx < 3; kx++)
                            acc[j][i] = fmaf(wv[ky * 3 + kx], r[ky][kx + i], acc[j][i]);
            }
        }
    }
    int pix0 = (y0 + y) * WW + x0 + qx * 4;
    #pragma unroll
    for (int j = 0; j < 4; j++) {
        int o = og + sub * 4 + j;
        float4 v4;
        float v;
        v = acc[j][0]; v4.x = (v >= 0.0f) ? v : alpha * v;
        v = acc[j][1]; v4.y = (v >= 0.0f) ? v : alpha * v;
        v = acc[j][2]; v4.z = (v >= 0.0f) ? v : alpha * v;
        v = acc[j][3]; v4.w = (v >= 0.0f) ? v : alpha * v;
        if (resid) {
            float4 rr = *(const float4*)(resid + o * NPIX + pix0);
            v4.x += rr.x; v4.y += rr.y; v4.z += rr.z; v4.w += rr.w;
        }
        *(float4*)(Out + o * NPIX + pix0) = v4;
    }
}

// ---------------- launch ----------------
extern "C" void kernel_launch(void* const* d_in, const int* in_sizes, int n_in,
                              void* d_out, int out_size) {
    const float* msi  = (const float*)d_in[0];
    const float* hsi  = (const float*)d_in[1];
    const float* W1a  = (const float*)d_in[2];
    const float* b1a  = (const float*)d_in[3];
    const float* a1a  = (const float*)d_in[4];
    const float* W1b  = (const float*)d_in[5];
    const float* b1b  = (const float*)d_in[6];
    const float* a1b  = (const float*)d_in[7];
    const float* W2a  = (const float*)d_in[8];
    const float* b2a  = (const float*)d_in[9];
    const float* a2a  = (const float*)d_in[10];
    const float* W2b  = (const float*)d_in[11];
    const float* b2b  = (const float*)d_in[12];
    const float* a2b  = (const float*)d_in[13];
    const float* Wg   = (const float*)d_in[14];
    const float* attl = (const float*)d_in[15];
    const float* attr = (const float*)d_in[16];
    const float* bg   = (const float*)d_in[17];
    const float* Ku1  = (const float*)d_in[18];
    const float* bu1  = (const float*)d_in[19];
    const float* au1  = (const float*)d_in[20];
    const float* Ku2  = (const float*)d_in[21];
    const float* bu2  = (const float*)d_in[22];
    const float* au2  = (const float*)d_in[23];

    float *p_hsi_up, *p_hfeat, *p_mfeat, *p_agg, *p_up1;
    unsigned short *p_hbf, *p_mbf;
    cudaGetSymbolAddress((void**)&p_hsi_up, g_hsi_up);
    cudaGetSymbolAddress((void**)&p_hfeat,  g_hfeat);
    cudaGetSymbolAddress((void**)&p_mfeat,  g_mfeat);
    cudaGetSymbolAddress((void**)&p_agg,    g_agg);
    cudaGetSymbolAddress((void**)&p_up1,    g_up1);
    cudaGetSymbolAddress((void**)&p_hbf,    g_hbf);
    cudaGetSymbolAddress((void**)&p_mbf,    g_mbf);

    k_bicubic<<<dim3(CCH, 4), 256>>>(hsi);

    k_embed<<<dim3(NPIX / 64, 2), 256>>>(p_hsi_up, msi,
                                         W1a, b1a, a1a, W1b, b1b, a1b,
                                         W2a, b2a, a2a, W2b, b2b, a2b,
                                         p_hfeat, p_mfeat, p_hbf, p_mbf);

    k_gatz<<<NPIX / 64, 256>>>(Wg, attl, attr);

    k_sim_hmma<<<dim3(72, SPLITS), 256>>>();
    k_rescore<<<NPIX / 8, 256>>>();

    k_edge_den<<<(ETOT + 255) / 256, 256>>>();
    k_selfagg<<<NPIX / 64, 256>>>(bg);
    k_edge_agg<<<(E5 * 4 + 255) / 256, 256>>>();

    k_conv3x3<<<dim3(6, 6, 4), 256>>>(p_agg, Ku1, bu1, au1, p_up1, nullptr);
    k_conv3x3<<<dim3(6, 6, 4), 256>>>(p_up1, Ku2, bu2, au2, (float*)d_out, p_hsi_up);
}